// round 1
// baseline (speedup 1.0000x reference)
#include <cuda_runtime.h>

#define N_NODES  10000
#define N_EDGES  640000
#define N_GRAPHS 64
#define F        128          // feature dim (in = hidden = 128)

// ---------------- scratch (no allocations allowed) ----------------
__device__ int   g_deg_out[N_NODES];
__device__ int   g_deg_in [N_NODES];
__device__ float g_norm_src[N_NODES];
__device__ float g_norm_dst[N_NODES];
__device__ int   g_row_ptr[N_NODES + 1];
__device__ int   g_cursor [N_NODES];
__device__ int   g_csr    [N_EDGES];       // src ids grouped by dst
__device__ float g_h1     [N_NODES * F];   // layer-1 output
__device__ float g_gsum   [N_GRAPHS];
__device__ int   g_gcnt   [N_GRAPHS];

// ---------------- init / degrees / norms ----------------
__global__ void k_init() {
    int i = blockIdx.x * blockDim.x + threadIdx.x;
    if (i < N_NODES) { g_deg_out[i] = 0; g_deg_in[i] = 0; }
    if (i < N_GRAPHS) { g_gsum[i] = 0.f; g_gcnt[i] = 0; }
}

__global__ void k_degree(const int* __restrict__ src, const int* __restrict__ dst) {
    int e = blockIdx.x * blockDim.x + threadIdx.x;
    if (e < N_EDGES) {
        atomicAdd(&g_deg_out[src[e]], 1);
        atomicAdd(&g_deg_in [dst[e]], 1);
    }
}

__global__ void k_norms(const int* __restrict__ gids) {
    int n = blockIdx.x * blockDim.x + threadIdx.x;
    if (n < N_NODES) {
        g_norm_src[n] = rsqrtf((float)max(g_deg_out[n], 1));
        g_norm_dst[n] = rsqrtf((float)max(g_deg_in [n], 1));
        atomicAdd(&g_gcnt[gids[n]], 1);
    }
}

// ---------------- single-block prefix sum over in-degrees ----------------
__global__ void k_scan() {
    const int T = 256, C = 40;              // 256*40 = 10240 >= N_NODES
    __shared__ int s[T];
    int t = threadIdx.x;
    int base = t * C;
    int local = 0;
    #pragma unroll
    for (int i = 0; i < C; i++) {
        int idx = base + i;
        if (idx < N_NODES) local += g_deg_in[idx];
    }
    s[t] = local;
    __syncthreads();
    for (int off = 1; off < T; off <<= 1) {  // inclusive Hillis-Steele
        int v = (t >= off) ? s[t - off] : 0;
        __syncthreads();
        s[t] += v;
        __syncthreads();
    }
    int run = (t == 0) ? 0 : s[t - 1];       // exclusive prefix of my chunk
    for (int i = 0; i < C; i++) {
        int idx = base + i;
        if (idx < N_NODES) {
            g_row_ptr[idx] = run;
            g_cursor [idx] = run;
            run += g_deg_in[idx];
        }
    }
    if (t == T - 1) g_row_ptr[N_NODES] = run; // = total edges
}

__global__ void k_scatter(const int* __restrict__ src, const int* __restrict__ dst) {
    int e = blockIdx.x * blockDim.x + threadIdx.x;
    if (e < N_EDGES) {
        int pos = atomicAdd(&g_cursor[dst[e]], 1);
        g_csr[pos] = src[e];
    }
}

// ---------------- fused layer: gather (CSR) + GEMM + bias + relu ----------------
// warp-per-node. Lane l owns output columns [4l, 4l+4).
// FUSE_POOL: instead of storing h, compute z = h . Wd, warp-reduce, atomicAdd to graph sum.
template <bool FUSE_POOL>
__global__ void k_layer(const float* __restrict__ x,
                        const float* __restrict__ W,
                        const float* __restrict__ b,
                        float* __restrict__ hout,
                        const float* __restrict__ Wd,
                        const int*  __restrict__ gids) {
    const int WARPS = 8;
    __shared__ float rowbuf[WARPS][F];
    int w    = threadIdx.x >> 5;
    int lane = threadIdx.x & 31;
    int n    = blockIdx.x * WARPS + w;
    if (n >= N_NODES) return;

    int beg = g_row_ptr[n], end = g_row_ptr[n + 1];
    const float4* X4 = (const float4*)x;

    float ax = 0.f, ay = 0.f, az = 0.f, aw = 0.f;
    int e = beg;
    // 4-way unroll: batch the dependent gathers for MLP
    for (; e + 4 <= end; e += 4) {
        int s0 = g_csr[e], s1 = g_csr[e + 1], s2 = g_csr[e + 2], s3 = g_csr[e + 3];
        float w0 = g_norm_src[s0], w1 = g_norm_src[s1],
              w2 = g_norm_src[s2], w3 = g_norm_src[s3];
        float4 x0 = X4[s0 * 32 + lane];
        float4 x1 = X4[s1 * 32 + lane];
        float4 x2 = X4[s2 * 32 + lane];
        float4 x3 = X4[s3 * 32 + lane];
        ax += w0 * x0.x + w1 * x1.x + w2 * x2.x + w3 * x3.x;
        ay += w0 * x0.y + w1 * x1.y + w2 * x2.y + w3 * x3.y;
        az += w0 * x0.z + w1 * x1.z + w2 * x2.z + w3 * x3.z;
        aw += w0 * x0.w + w1 * x1.w + w2 * x2.w + w3 * x3.w;
    }
    for (; e < end; e++) {
        int s = g_csr[e];
        float ws = g_norm_src[s];
        float4 xv = X4[s * 32 + lane];
        ax += ws * xv.x; ay += ws * xv.y; az += ws * xv.z; aw += ws * xv.w;
    }

    float nd = g_norm_dst[n];
    rowbuf[w][lane * 4 + 0] = ax * nd;
    rowbuf[w][lane * 4 + 1] = ay * nd;
    rowbuf[w][lane * 4 + 2] = az * nd;
    rowbuf[w][lane * 4 + 3] = aw * nd;
    __syncwarp();

    // GEMM: o[c] = sum_k row[k] * W[k][c] + b[c]
    const float4* W4 = (const float4*)W;
    float4 bv = ((const float4*)b)[lane];
    float ox = bv.x, oy = bv.y, oz = bv.z, ow = bv.w;
    #pragma unroll 16
    for (int k = 0; k < F; k++) {
        float av  = rowbuf[w][k];              // LDS broadcast
        float4 wv = W4[k * 32 + lane];         // L1-resident after warmup
        ox += av * wv.x; oy += av * wv.y; oz += av * wv.z; ow += av * wv.w;
    }
    ox = fmaxf(ox, 0.f); oy = fmaxf(oy, 0.f);
    oz = fmaxf(oz, 0.f); ow = fmaxf(ow, 0.f);

    if (!FUSE_POOL) {
        ((float4*)hout)[n * 32 + lane] = make_float4(ox, oy, oz, ow);
    } else {
        float4 wd = ((const float4*)Wd)[lane];
        float z = ox * wd.x + oy * wd.y + oz * wd.z + ow * wd.w;
        #pragma unroll
        for (int off = 16; off > 0; off >>= 1)
            z += __shfl_xor_sync(0xffffffffu, z, off);
        if (lane == 0) atomicAdd(&g_gsum[gids[n]], z);
    }
}

__global__ void k_final(const float* __restrict__ bd, float* __restrict__ out) {
    int g = threadIdx.x;
    if (g < N_GRAPHS)
        out[g] = g_gsum[g] / fmaxf((float)g_gcnt[g], 1.f) + bd[0];
}

// ---------------- launch ----------------
extern "C" void kernel_launch(void* const* d_in, const int* in_sizes, int n_in,
                              void* d_out, int out_size) {
    const float* in_feat = (const float*)d_in[0];
    const int*   src     = (const int*)  d_in[1];
    const int*   dst     = (const int*)  d_in[2];
    const int*   gids    = (const int*)  d_in[3];
    const float* W1      = (const float*)d_in[4];
    const float* b1      = (const float*)d_in[5];
    const float* W2      = (const float*)d_in[6];
    const float* b2      = (const float*)d_in[7];
    const float* Wd      = (const float*)d_in[8];
    const float* bd      = (const float*)d_in[9];
    float* out = (float*)d_out;

    const int TB = 256;
    int nodeBlocks = (N_NODES + TB - 1) / TB;
    int edgeBlocks = (N_EDGES + TB - 1) / TB;
    int layerBlocks = (N_NODES + 8 - 1) / 8;   // warp-per-node, 8 warps/block

    k_init<<<nodeBlocks, TB>>>();
    k_degree<<<edgeBlocks, TB>>>(src, dst);
    k_norms<<<nodeBlocks, TB>>>(gids);
    k_scan<<<1, 256>>>();
    k_scatter<<<edgeBlocks, TB>>>(src, dst);
    k_layer<false><<<layerBlocks, TB>>>(in_feat, W1, b1, g_h1, nullptr, nullptr);
    k_layer<true ><<<layerBlocks, TB>>>(g_h1,    W2, b2, nullptr, Wd, gids);
    k_final<<<1, 64>>>(bd, out);
}